// round 16
// baseline (speedup 1.0000x reference)
#include <cuda_runtime.h>
#include <cuda_bf16.h>
#include <math.h>
#include <stdint.h>

#define NUM_USERS 100000
#define NUM_ITEMS 50000
#define N_NODES   150000
#define EMBED     128
#define N_EDGES   1000000
#define N_SYM     (2*N_EDGES)
#define HID       128
#define NUM_CAT   100
#define NUM_SKU   2000
#define HPITCH    384

// ---------------- static device scratch ----------------
__device__ int   g_deg[N_NODES];
__device__ int   g_off[N_NODES + 1];
__device__ int   g_cur[N_NODES];
__device__ int   g_adj_col[N_SYM];
__device__ float g_adj_w[N_SYM];
__device__ __align__(16) float g_e1[(size_t)N_NODES * EMBED];
__device__ __align__(16) float g_e2[(size_t)N_NODES * EMBED];
__device__ int   g_bsum[256];
__device__ float g_bias1[HPITCH];
// bf16 split operand buffers
__device__ __align__(16) __nv_bfloat16 g_Uhi[(size_t)NUM_USERS * EMBED];
__device__ __align__(16) __nv_bfloat16 g_Ulo[(size_t)NUM_USERS * EMBED];
__device__ __align__(16) __nv_bfloat16 g_Hhi[(size_t)NUM_USERS * HPITCH];
__device__ __align__(16) __nv_bfloat16 g_Hlo[(size_t)NUM_USERS * HPITCH];
__device__ __align__(16) __nv_bfloat16 g_Bthi[2560 * 128];   // transposed weights [n][k]
__device__ __align__(16) __nv_bfloat16 g_Btlo[2560 * 128];

#define T_SCAN 1024

// ================= warp-MMA / cp.async helpers =================
__device__ __forceinline__ uint32_t smem_u32(const void* p) {
    uint32_t a;
    asm("{ .reg .u64 t; cvta.to.shared.u64 t, %1; cvt.u32.u64 %0, t; }" : "=r"(a) : "l"(p));
    return a;
}
__device__ __forceinline__ void ldsm_x4(uint32_t r[4], uint32_t addr) {
    asm volatile("ldmatrix.sync.aligned.m8n8.x4.shared.b16 {%0,%1,%2,%3}, [%4];"
                 : "=r"(r[0]), "=r"(r[1]), "=r"(r[2]), "=r"(r[3]) : "r"(addr));
}
__device__ __forceinline__ void ldsm_x2(uint32_t r[2], uint32_t addr) {
    asm volatile("ldmatrix.sync.aligned.m8n8.x2.shared.b16 {%0,%1}, [%2];"
                 : "=r"(r[0]), "=r"(r[1]) : "r"(addr));
}
__device__ __forceinline__ void mma_bf16(float c[4], const uint32_t a[4], const uint32_t b[2]) {
    asm volatile("mma.sync.aligned.m16n8k16.row.col.f32.bf16.bf16.f32 "
                 "{%0,%1,%2,%3}, {%4,%5,%6,%7}, {%8,%9}, {%0,%1,%2,%3};"
                 : "+f"(c[0]), "+f"(c[1]), "+f"(c[2]), "+f"(c[3])
                 : "r"(a[0]), "r"(a[1]), "r"(a[2]), "r"(a[3]), "r"(b[0]), "r"(b[1]));
}
// 16B async copy with zero-fill fallback for invalid rows
__device__ __forceinline__ void cp16z(uint32_t dst, const void* src, bool v) {
    if (v) {
        asm volatile("cp.async.cg.shared.global [%0], [%1], 16;" :: "r"(dst), "l"(src) : "memory");
    } else {
        asm volatile("st.shared.v4.b32 [%0], {%1,%1,%1,%1};" :: "r"(dst), "r"(0u) : "memory");
    }
}
#define CP_COMMIT() asm volatile("cp.async.commit_group;" ::: "memory")
#define CP_WAIT0()  asm volatile("cp.async.wait_group 0;" ::: "memory")

// fma helper (function, not macro — avoids token collision with .w member)
__device__ __forceinline__ void fma4(float4& acc, float wt, const float4& v) {
    acc.x = fmaf(wt, v.x, acc.x);
    acc.y = fmaf(wt, v.y, acc.y);
    acc.z = fmaf(wt, v.z, acc.z);
    acc.w = fmaf(wt, v.w, acc.w);
}
// streaming stores (cache .cs — evict-first; output streams never re-read)
__device__ __forceinline__ void stcs4(float4* p, float4 v) {
    asm volatile("st.global.cs.v4.f32 [%0], {%1,%2,%3,%4};"
                 :: "l"(p), "f"(v.x), "f"(v.y), "f"(v.z), "f"(v.w) : "memory");
}
__device__ __forceinline__ void stcs2(float* p, float2 v) {
    asm volatile("st.global.cs.v2.f32 [%0], {%1,%2};"
                 :: "l"(p), "f"(v.x), "f"(v.y) : "memory");
}
__device__ __forceinline__ void stcs1(float* p, float v) {
    asm volatile("st.global.cs.f32 [%0], %1;" :: "l"(p), "f"(v) : "memory");
}

// ---------------- graph build ----------------
__global__ void k_zero() {
    int i = blockIdx.x * blockDim.x + threadIdx.x;
    if (i < N_NODES) { g_deg[i] = 0; g_cur[i] = 0; }
}
__global__ void k_deg(const int* __restrict__ ei) {
    int e = blockIdx.x * blockDim.x + threadIdx.x;
    if (e < N_EDGES) {
        atomicAdd(&g_deg[ei[e]], 1);
        atomicAdd(&g_deg[ei[N_EDGES + e]], 1);
    }
}
__global__ void k_scan_part() {
    __shared__ int s[T_SCAN];
    int t = threadIdx.x, b = blockIdx.x;
    int i = b * T_SCAN + t;
    int v = (i < N_NODES) ? g_deg[i] : 0;
    s[t] = v;
    __syncthreads();
    for (int d = 1; d < T_SCAN; d <<= 1) {
        int x = (t >= d) ? s[t - d] : 0;
        __syncthreads();
        s[t] += x;
        __syncthreads();
    }
    if (i < N_NODES) g_off[i] = s[t] - v;
    if (t == T_SCAN - 1) g_bsum[b] = s[t];
}
__global__ void k_scan_base2(int nb) {
    __shared__ int s[256];
    int t = threadIdx.x;
    int v = (t < nb) ? g_bsum[t] : 0;
    s[t] = v;
    __syncthreads();
    for (int d = 1; d < 256; d <<= 1) {
        int x = (t >= d) ? s[t - d] : 0;
        __syncthreads();
        s[t] += x;
        __syncthreads();
    }
    if (t < nb) g_bsum[t] = s[t] - v;   // exclusive
    if (t == 255) g_off[N_NODES] = s[255];
}
__global__ void k_scan_add() {
    int i = blockIdx.x * T_SCAN + threadIdx.x;
    if (i < N_NODES) g_off[i] += g_bsum[blockIdx.x];
}
__global__ void k_fill(const int* __restrict__ ei) {
    int e = blockIdx.x * blockDim.x + threadIdx.x;
    if (e >= N_EDGES) return;
    int r = ei[e];
    int c = ei[N_EDGES + e];
    float nrm = rsqrtf((float)g_deg[r]) * rsqrtf((float)g_deg[c]);
    int p = atomicAdd(&g_cur[r], 1);
    g_adj_col[g_off[r] + p] = c; g_adj_w[g_off[r] + p] = nrm;
    int q = atomicAdd(&g_cur[c], 1);
    g_adj_col[g_off[c] + q] = r; g_adj_w[g_off[c] + q] = nrm;
}

// ---------------- propagation: one warp per row, float4 lanes ----------------
__device__ __forceinline__ float4 prop_row(const float4* __restrict__ src, int row, int lane) {
    int s = g_off[row], e2 = g_off[row + 1];
    float4 a = make_float4(0.f, 0.f, 0.f, 0.f);
    int e = s;
    for (; e + 4 <= e2; e += 4) {
        int   c0 = g_adj_col[e],   c1 = g_adj_col[e+1], c2 = g_adj_col[e+2], c3 = g_adj_col[e+3];
        float w0 = g_adj_w[e],     w1 = g_adj_w[e+1],   w2 = g_adj_w[e+2],   w3 = g_adj_w[e+3];
        float4 v0 = src[c0 * 32 + lane];
        float4 v1 = src[c1 * 32 + lane];
        float4 v2 = src[c2 * 32 + lane];
        float4 v3 = src[c3 * 32 + lane];
        fma4(a, w0, v0); fma4(a, w1, v1); fma4(a, w2, v2); fma4(a, w3, v3);
    }
    for (; e < e2; e++) {
        float4 v = src[g_adj_col[e] * 32 + lane];
        fma4(a, g_adj_w[e], v);
    }
    return a;
}

// layer-1: gather directly from ue/it (no e0 buffer)
__device__ __forceinline__ const float4* node_ptr(const float4* __restrict__ ue,
                                                  const float4* __restrict__ it, int c) {
    return (c < NUM_USERS) ? (ue + (size_t)c * 32) : (it + ((size_t)c - NUM_USERS) * 32);
}

__global__ void k_prop4_init(const float4* __restrict__ ue, const float4* __restrict__ it,
                             float4* __restrict__ dst, int nrows) {
    int warp = (blockIdx.x * blockDim.x + threadIdx.x) >> 5;
    int lane = threadIdx.x & 31;
    if (warp >= nrows) return;
    int s = g_off[warp], e2 = g_off[warp + 1];
    float4 a = make_float4(0.f, 0.f, 0.f, 0.f);
    int e = s;
    for (; e + 4 <= e2; e += 4) {
        int   c0 = g_adj_col[e],   c1 = g_adj_col[e+1], c2 = g_adj_col[e+2], c3 = g_adj_col[e+3];
        float w0 = g_adj_w[e],     w1 = g_adj_w[e+1],   w2 = g_adj_w[e+2],   w3 = g_adj_w[e+3];
        float4 v0 = node_ptr(ue, it, c0)[lane];
        float4 v1 = node_ptr(ue, it, c1)[lane];
        float4 v2 = node_ptr(ue, it, c2)[lane];
        float4 v3 = node_ptr(ue, it, c3)[lane];
        fma4(a, w0, v0); fma4(a, w1, v1); fma4(a, w2, v2); fma4(a, w3, v3);
    }
    for (; e < e2; e++) {
        float4 v = node_ptr(ue, it, g_adj_col[e])[lane];
        fma4(a, g_adj_w[e], v);
    }
    stcs4(&dst[warp * 32 + lane], a);
}

__global__ void k_prop4(const float4* __restrict__ src, float4* __restrict__ dst, int nrows) {
    int warp = (blockIdx.x * blockDim.x + threadIdx.x) >> 5;
    int lane = threadIdx.x & 31;
    if (warp >= nrows) return;
    float4 a = prop_row(src, warp, lane);
    stcs4(&dst[warp * 32 + lane], a);
}

// final layer (users only): a = prop(e2); u = (ue+e1+e2+a)/4; write u fp32 + bf16 hi/lo
__global__ void k_prop_final(const float4* __restrict__ ue, const float4* __restrict__ e1,
                             const float4* __restrict__ e2, float4* __restrict__ uo) {
    int warp = (blockIdx.x * blockDim.x + threadIdx.x) >> 5;
    int lane = threadIdx.x & 31;
    if (warp >= NUM_USERS) return;
    float4 a = prop_row(e2, warp, lane);
    float4 v0 = ue[warp * 32 + lane];
    float4 v1 = e1[warp * 32 + lane];
    float4 v2 = e2[warp * 32 + lane];
    float4 u;
    u.x = (v0.x + v1.x + v2.x + a.x) * 0.25f;
    u.y = (v0.y + v1.y + v2.y + a.y) * 0.25f;
    u.z = (v0.z + v1.z + v2.z + a.z) * 0.25f;
    u.w = (v0.w + v1.w + v2.w + a.w) * 0.25f;
    stcs4(&uo[warp * 32 + lane], u);
    __nv_bfloat16 h0 = __float2bfloat16(u.x), h1 = __float2bfloat16(u.y);
    __nv_bfloat16 h2 = __float2bfloat16(u.z), h3 = __float2bfloat16(u.w);
    __nv_bfloat16 l0 = __float2bfloat16(u.x - __bfloat162float(h0));
    __nv_bfloat16 l1 = __float2bfloat16(u.y - __bfloat162float(h1));
    __nv_bfloat16 l2 = __float2bfloat16(u.z - __bfloat162float(h2));
    __nv_bfloat16 l3 = __float2bfloat16(u.w - __bfloat162float(h3));
    __nv_bfloat162 hp0 = {h0, h1}, hp1 = {h2, h3};
    __nv_bfloat162 lp0 = {l0, l1}, lp1 = {l2, l3};
    uint2 hv, lv;
    hv.x = *(uint32_t*)&hp0; hv.y = *(uint32_t*)&hp1;
    lv.x = *(uint32_t*)&lp0; lv.y = *(uint32_t*)&lp1;
    *(uint2*)&g_Uhi[(size_t)warp * 128 + lane * 4] = hv;
    *(uint2*)&g_Ulo[(size_t)warp * 128 + lane * 4] = lv;
}

// weights: B [K=128, N] row-major -> transposed bf16 hi/lo rows [dstOff+n][k]
__global__ void k_prepB(const float* __restrict__ B, int N, int dstOff) {
    int i = blockIdx.x * blockDim.x + threadIdx.x;
    if (i >= N * 128) return;
    int n = i >> 7, k = i & 127;
    float v = B[(size_t)k * N + n];
    __nv_bfloat16 h = __float2bfloat16(v);
    g_Bthi[(dstOff + n) * 128 + k] = h;
    g_Btlo[(dstOff + n) * 128 + k] = __float2bfloat16(v - __bfloat162float(h));
}
__global__ void k_bias1(const float* __restrict__ b0, const float* __restrict__ b1,
                        const float* __restrict__ b2) {
    int i = threadIdx.x;
    g_bias1[i] = (i < 128) ? b0[i] : ((i < 256) ? b1[i - 128] : b2[i - 256]);
}

// ---------------- warp-MMA bf16-split GEMM, 128x128 tile (layer-1, heads fused) ----------------
// MODE 1, grid (3, MT): blockIdx.x==0 -> fused churn head; ==1 -> fused cat head (second
// in-smem GEMM vs catW2 at g_Bt rows [384,484)); ==2 -> bf16 hi/lo H planes for sku.
#define SA_HI 0
#define SA_LO 16384
#define SB_HI 32768
#define SB_LO 49152
// fused-cat phase overlays:
#define FC_HH  0        // 32 KB: H hi plane, 2 kt blocks of 16 KB
#define FC_HL  32768    // 32 KB: H lo plane
#define FC_B2H 65536    // 16 KB: catW2 hi, one kt-half
#define FC_B2L 81920    // 16 KB
#define OPITCH 132
#define SMEM_MMA 98304

template <int ACT, int MODE>
__global__ void __launch_bounds__(256, 2) k_tmma(
    const __nv_bfloat16* __restrict__ Ahi, const __nv_bfloat16* __restrict__ Alo, int lda,
    const float* __restrict__ bias, float* __restrict__ C, int ldC,
    __nv_bfloat16* __restrict__ Phi, __nv_bfloat16* __restrict__ Plo, int ldP,
    int M, int N,
    const float* __restrict__ churn_w2, const float* __restrict__ churn_b2,
    float* __restrict__ churn_out,
    const float* __restrict__ cat_bias, float* __restrict__ cat_out)
{
    extern __shared__ char sm[];
    const uint32_t sb = smem_u32(sm);
    const int tid  = threadIdx.x;
    const int wid  = tid >> 5;
    const int lane = tid & 31;
    const int bm = blockIdx.y * 128;
    const int bn = blockIdx.x * 128;
    const int wm = (wid >> 2) * 64;
    const int wn = (wid & 3) * 32;

    float acc[4][4][4];
    #pragma unroll
    for (int i = 0; i < 4; i++)
        #pragma unroll
        for (int j = 0; j < 4; j++)
            #pragma unroll
            for (int t = 0; t < 4; t++) acc[i][j][t] = 0.f;

    for (int kt = 0; kt < 128; kt += 64) {
        #pragma unroll
        for (int it = 0; it < 4; it++) {
            int idx = tid + it * 256;
            int r = idx >> 3, c = idx & 7;
            uint32_t dst = (uint32_t)(r * 128 + ((c ^ (r & 7)) << 4));
            int gr = bm + r;
            bool av = gr < M;
            cp16z(sb + SA_HI + dst, Ahi + (size_t)gr * lda + kt + c * 8, av);
            cp16z(sb + SA_LO + dst, Alo + (size_t)gr * lda + kt + c * 8, av);
            int gn = bn + r;
            bool bv = gn < N;
            cp16z(sb + SB_HI + dst, g_Bthi + (size_t)gn * 128 + kt + c * 8, bv);
            cp16z(sb + SB_LO + dst, g_Btlo + (size_t)gn * 128 + kt + c * 8, bv);
        }
        CP_COMMIT();
        CP_WAIT0();
        __syncthreads();

        #pragma unroll
        for (int ks = 0; ks < 4; ks++) {
            const int k0 = ks * 16;
            uint32_t bh[4][2], bl[4][2];
            const int k_l = k0 + ((lane & 8) ? 8 : 0);
            #pragma unroll
            for (int j = 0; j < 4; j++) {
                int row = wn + j * 8 + (lane & 7);
                uint32_t off = (uint32_t)(row * 128 + (((k_l >> 3) ^ (row & 7)) << 4));
                ldsm_x2(bh[j], sb + SB_HI + off);
                ldsm_x2(bl[j], sb + SB_LO + off);
            }
            #pragma unroll
            for (int mi = 0; mi < 4; mi++) {
                const int m_l = wm + mi * 16 + (lane & 7) + (lane & 8);
                const int k_a = k0 + ((lane & 16) ? 8 : 0);
                const uint32_t off = (uint32_t)(m_l * 128 + (((k_a >> 3) ^ (m_l & 7)) << 4));
                uint32_t ah[4], al[4];
                ldsm_x4(ah, sb + SA_HI + off);
                ldsm_x4(al, sb + SA_LO + off);
                #pragma unroll
                for (int j = 0; j < 4; j++) {
                    mma_bf16(acc[mi][j], ah, bh[j]);
                    mma_bf16(acc[mi][j], al, bh[j]);
                    mma_bf16(acc[mi][j], ah, bl[j]);
                }
            }
        }
        __syncthreads();
    }

    // ---- fused churn head (blockIdx.x == 0 of layer-1) ----
    if (MODE == 1 && churn_out != nullptr && blockIdx.x == 0) {
        float* churnS = (float*)sm;
        if (tid < 128) churnS[tid] = 0.f;
        __syncthreads();
        #pragma unroll
        for (int mi = 0; mi < 4; mi++) {
            float p0 = 0.f, p1 = 0.f;   // rows r0 and r0+8
            #pragma unroll
            for (int j = 0; j < 4; j++) {
                int c0 = wn + j * 8 + 2 * (lane & 3);
                float wv0 = __ldg(&churn_w2[c0]);
                float wv1 = __ldg(&churn_w2[c0 + 1]);
                float b0 = __ldg(&bias[c0]);
                float b1 = __ldg(&bias[c0 + 1]);
                float x00 = fmaxf(acc[mi][j][0] + b0, 0.f);
                float x01 = fmaxf(acc[mi][j][1] + b1, 0.f);
                float x10 = fmaxf(acc[mi][j][2] + b0, 0.f);
                float x11 = fmaxf(acc[mi][j][3] + b1, 0.f);
                p0 = fmaf(x00, wv0, p0); p0 = fmaf(x01, wv1, p0);
                p1 = fmaf(x10, wv0, p1); p1 = fmaf(x11, wv1, p1);
            }
            p0 += __shfl_xor_sync(0xFFFFFFFF, p0, 1);
            p0 += __shfl_xor_sync(0xFFFFFFFF, p0, 2);
            p1 += __shfl_xor_sync(0xFFFFFFFF, p1, 1);
            p1 += __shfl_xor_sync(0xFFFFFFFF, p1, 2);
            if ((lane & 3) == 0) {
                int r0 = wm + mi * 16 + (lane >> 2);
                atomicAdd(&churnS[r0], p0);
                atomicAdd(&churnS[r0 + 8], p1);
            }
        }
        __syncthreads();
        if (tid < 128) {
            int m = bm + tid;
            if (m < M)
                churn_out[m] = 1.f / (1.f + __expf(-(churnS[tid] + churn_b2[0])));
        }
        return;
    }

    // ---- fused cat head (blockIdx.x == 1 of layer-1) ----
    if (MODE == 1 && cat_out != nullptr && blockIdx.x == 1) {
        // stage relu(H + bias) as swizzled bf16 hi/lo planes (full K=128, 2 kt blocks)
        #pragma unroll
        for (int mi = 0; mi < 4; mi++) {
            const int r0 = wm + mi * 16 + (lane >> 2);
            #pragma unroll
            for (int j = 0; j < 4; j++) {
                const int c0 = wn + j * 8 + 2 * (lane & 3);
                float b0 = __ldg(&bias[128 + c0]);
                float b1 = __ldg(&bias[128 + c0 + 1]);
                const int ktb = c0 >> 6, cc = c0 & 63;
                #pragma unroll
                for (int h = 0; h < 2; h++) {
                    int r = r0 + 8 * h;
                    float x0 = fmaxf(acc[mi][j][2 * h + 0] + b0, 0.f);
                    float x1 = fmaxf(acc[mi][j][2 * h + 1] + b1, 0.f);
                    __nv_bfloat16 h0 = __float2bfloat16(x0), h1 = __float2bfloat16(x1);
                    __nv_bfloat16 l0 = __float2bfloat16(x0 - __bfloat162float(h0));
                    __nv_bfloat16 l1 = __float2bfloat16(x1 - __bfloat162float(h1));
                    __nv_bfloat162 hp = {h0, h1}, lp = {l0, l1};
                    uint32_t off = (uint32_t)(ktb * 16384 + r * 128 +
                                              (((cc >> 3) ^ (r & 7)) << 4) + (cc & 7) * 2);
                    *(uint32_t*)(sm + FC_HH + off) = *(uint32_t*)&hp;
                    *(uint32_t*)(sm + FC_HL + off) = *(uint32_t*)&lp;
                }
            }
        }
        // second GEMM: cat = H @ catW2^T   (catW2 bf16-split at g_Bt rows [384,484))
        float acc2[4][4][4];
        #pragma unroll
        for (int i = 0; i < 4; i++)
            #pragma unroll
            for (int j = 0; j < 4; j++)
                #pragma unroll
                for (int t = 0; t < 4; t++) acc2[i][j][t] = 0.f;

        #pragma unroll
        for (int ktb = 0; ktb < 2; ktb++) {
            __syncthreads();   // H staged (ktb=0) / protect B2 buffer from prev readers
            #pragma unroll
            for (int it = 0; it < 4; it++) {
                int idx = tid + it * 256;
                int r = idx >> 3, c = idx & 7;
                uint32_t dst = (uint32_t)(r * 128 + ((c ^ (r & 7)) << 4));
                bool bv = r < NUM_CAT;
                cp16z(sb + FC_B2H + dst, g_Bthi + (size_t)(384 + r) * 128 + ktb * 64 + c * 8, bv);
                cp16z(sb + FC_B2L + dst, g_Btlo + (size_t)(384 + r) * 128 + ktb * 64 + c * 8, bv);
            }
            CP_COMMIT();
            CP_WAIT0();
            __syncthreads();

            #pragma unroll
            for (int ks = 0; ks < 4; ks++) {
                const int k0 = ks * 16;
                uint32_t bh[4][2], bl[4][2];
                const int k_l = k0 + ((lane & 8) ? 8 : 0);
                #pragma unroll
                for (int j = 0; j < 4; j++) {
                    int row = wn + j * 8 + (lane & 7);
                    uint32_t off = (uint32_t)(row * 128 + (((k_l >> 3) ^ (row & 7)) << 4));
                    ldsm_x2(bh[j], sb + FC_B2H + off);
                    ldsm_x2(bl[j], sb + FC_B2L + off);
                }
                #pragma unroll
                for (int mi = 0; mi < 4; mi++) {
                    const int m_l = wm + mi * 16 + (lane & 7) + (lane & 8);
                    const int k_a = k0 + ((lane & 16) ? 8 : 0);
                    const uint32_t off = (uint32_t)(ktb * 16384 + m_l * 128 +
                                                    (((k_a >> 3) ^ (m_l & 7)) << 4));
                    uint32_t ah[4], al[4];
                    ldsm_x4(ah, sb + FC_HH + off);
                    ldsm_x4(al, sb + FC_HL + off);
                    #pragma unroll
                    for (int j = 0; j < 4; j++) {
                        mma_bf16(acc2[mi][j], ah, bh[j]);
                        mma_bf16(acc2[mi][j], al, bh[j]);
                        mma_bf16(acc2[mi][j], ah, bl[j]);
                    }
                }
            }
        }
        __syncthreads();   // all smem MMA reads done before outS overwrites H region

        // epilogue: sigmoid -> staged smem -> coalesced fp32 stores (N = NUM_CAT)
        float* outS = (float*)sm;
        #pragma unroll
        for (int mi = 0; mi < 4; mi++) {
            const int r0 = wm + mi * 16 + (lane >> 2);
            #pragma unroll
            for (int j = 0; j < 4; j++) {
                const int c0 = wn + j * 8 + 2 * (lane & 3);
                float b0 = (c0     < NUM_CAT) ? __ldg(&cat_bias[c0])     : 0.f;
                float b1 = (c0 + 1 < NUM_CAT) ? __ldg(&cat_bias[c0 + 1]) : 0.f;
                #pragma unroll
                for (int h = 0; h < 2; h++) {
                    float x0 = acc2[mi][j][2 * h + 0] + b0;
                    float x1 = acc2[mi][j][2 * h + 1] + b1;
                    x0 = 1.f / (1.f + __expf(-x0));
                    x1 = 1.f / (1.f + __expf(-x1));
                    outS[(r0 + 8 * h) * OPITCH + c0]     = x0;
                    outS[(r0 + 8 * h) * OPITCH + c0 + 1] = x1;
                }
            }
        }
        __syncthreads();
        for (int idx = tid; idx < 128 * 32; idx += 256) {
            int r = idx >> 5;
            int col = (idx & 31) * 4;
            int m = bm + r;
            if (m >= M || col >= NUM_CAT) continue;
            float4 v = *(float4*)&outS[r * OPITCH + col];
            stcs4((float4*)&cat_out[(size_t)m * NUM_CAT + col], v);
        }
        return;
    }

    // ---- standard epilogue: bias + act -> smem staging -> coalesced stores ----
    float* outS = (float*)sm;
    #pragma unroll
    for (int mi = 0; mi < 4; mi++) {
        const int r0 = wm + mi * 16 + (lane >> 2);
        #pragma unroll
        for (int j = 0; j < 4; j++) {
            const int c0 = wn + j * 8 + 2 * (lane & 3);
            float b0 = (bn + c0     < N) ? __ldg(&bias[bn + c0])     : 0.f;
            float b1 = (bn + c0 + 1 < N) ? __ldg(&bias[bn + c0 + 1]) : 0.f;
            #pragma unroll
            for (int h = 0; h < 2; h++) {
                float x0 = acc[mi][j][2 * h + 0] + b0;
                float x1 = acc[mi][j][2 * h + 1] + b1;
                if (ACT == 0) { x0 = fmaxf(x0, 0.f); x1 = fmaxf(x1, 0.f); }
                else { x0 = 1.f / (1.f + __expf(-x0)); x1 = 1.f / (1.f + __expf(-x1)); }
                outS[(r0 + 8 * h) * OPITCH + c0]     = x0;
                outS[(r0 + 8 * h) * OPITCH + c0 + 1] = x1;
            }
        }
    }
    __syncthreads();

    const int Nvalid = min(128, N - bn);
    for (int idx = tid; idx < 128 * 32; idx += 256) {
        int r = idx >> 5;
        int col = (idx & 31) * 4;
        int m = bm + r;
        if (m >= M || col >= Nvalid) continue;
        float4 v = *(float4*)&outS[r * OPITCH + col];
        if (MODE == 0) {
            *(float4*)&C[(size_t)m * ldC + bn + col] = v;
        } else {
            __nv_bfloat16 h0 = __float2bfloat16(v.x), h1 = __float2bfloat16(v.y);
            __nv_bfloat16 h2 = __float2bfloat16(v.z), h3 = __float2bfloat16(v.w);
            __nv_bfloat16 l0 = __float2bfloat16(v.x - __bfloat162float(h0));
            __nv_bfloat16 l1 = __float2bfloat16(v.y - __bfloat162float(h1));
            __nv_bfloat16 l2 = __float2bfloat16(v.z - __bfloat162float(h2));
            __nv_bfloat16 l3 = __float2bfloat16(v.w - __bfloat162float(h3));
            __nv_bfloat162 hp0 = {h0, h1}, hp1 = {h2, h3};
            __nv_bfloat162 lp0 = {l0, l1}, lp1 = {l2, l3};
            uint2 hv, lv;
            hv.x = *(uint32_t*)&hp0; hv.y = *(uint32_t*)&hp1;
            lv.x = *(uint32_t*)&lp0; lv.y = *(uint32_t*)&lp1;
            *(uint2*)&Phi[(size_t)m * ldP + bn + col] = hv;
            *(uint2*)&Plo[(size_t)m * ldP + bn + col] = lv;
        }
    }
}

// ---------------- sku layer-2: A-resident N-loop GEMM, 128x128 tiles, SK_NT tiles/CTA ----------------
#define SK_AHI 0          // 2 kt blocks of 16KB -> 32KB
#define SK_ALO 32768      // 32KB
#define SK_BHI 65536      // 16KB
#define SK_BLO 81920      // 16KB
#define SMEM_SKU 98304
#define SK_NT 8

__global__ void __launch_bounds__(256, 2) k_tmma_sku(
    const __nv_bfloat16* __restrict__ Ahi, const __nv_bfloat16* __restrict__ Alo, int lda,
    const float* __restrict__ bias, float* __restrict__ C, int ldC,
    int M, int N)
{
    extern __shared__ char sm[];
    const uint32_t sb = smem_u32(sm);
    const int tid  = threadIdx.x;
    const int wid  = tid >> 5;
    const int lane = tid & 31;
    const int bm = blockIdx.y * 128;
    const int bn0 = blockIdx.x * (SK_NT * 128);
    const int wm = (wid >> 2) * 64;
    const int wn = (wid & 3) * 32;

    // ---- load A tile once: full K=128, hi+lo planes (kt blocks stacked) ----
    #pragma unroll
    for (int it = 0; it < 8; it++) {
        int idx = tid + it * 256;          // 0..2047 per plane
        int r = idx >> 4, cc = idx & 15;
        int ktb = cc >> 3, c = cc & 7;
        uint32_t dst = (uint32_t)(ktb * 16384 + r * 128 + ((c ^ (r & 7)) << 4));
        int gr = bm + r;
        bool av = gr < M;
        cp16z(sb + SK_AHI + dst, Ahi + (size_t)gr * lda + ktb * 64 + c * 8, av);
        cp16z(sb + SK_ALO + dst, Alo + (size_t)gr * lda + ktb * 64 + c * 8, av);
    }
    CP_COMMIT();

    for (int nt = 0; nt < SK_NT; nt++) {
        const int bn = bn0 + nt * 128;

        float acc[4][4][4];
        #pragma unroll
        for (int i = 0; i < 4; i++)
            #pragma unroll
            for (int j = 0; j < 4; j++)
                #pragma unroll
                for (int t = 0; t < 4; t++) acc[i][j][t] = 0.f;

        #pragma unroll
        for (int ktb = 0; ktb < 2; ktb++) {
            __syncthreads();   // protect B buffer from previous iteration's readers
            #pragma unroll
            for (int it = 0; it < 4; it++) {
                int idx = tid + it * 256;     // 0..1023 per plane
                int r = idx >> 3, c = idx & 7;
                uint32_t dst = (uint32_t)(r * 128 + ((c ^ (r & 7)) << 4));
                int gn = bn + r;
                bool bv = gn < N;
                cp16z(sb + SK_BHI + dst, g_Bthi + (size_t)gn * 128 + ktb * 64 + c * 8, bv);
                cp16z(sb + SK_BLO + dst, g_Btlo + (size_t)gn * 128 + ktb * 64 + c * 8, bv);
            }
            CP_COMMIT();
            CP_WAIT0();        // waits B (and A on first pass)
            __syncthreads();

            #pragma unroll
            for (int ks = 0; ks < 4; ks++) {
                const int k0 = ks * 16;
                uint32_t bh[4][2], bl[4][2];
                const int k_l = k0 + ((lane & 8) ? 8 : 0);
                #pragma unroll
                for (int j = 0; j < 4; j++) {
                    int row = wn + j * 8 + (lane & 7);
                    uint32_t off = (uint32_t)(row * 128 + (((k_l >> 3) ^ (row & 7)) << 4));
                    ldsm_x2(bh[j], sb + SK_BHI + off);
                    ldsm_x2(bl[j], sb + SK_BLO + off);
                }
                #pragma unroll
                for (int mi = 0; mi < 4; mi++) {
                    const int m_l = wm + mi * 16 + (lane & 7) + (lane & 8);
                    const int k_a = k0 + ((lane & 16) ? 8 : 0);
                    const uint32_t off = (uint32_t)(ktb * 16384 + m_l * 128 + (((k_a >> 3) ^ (m_l & 7)) << 4));
                    uint32_t ah[4], al[4];
                    ldsm_x4(ah, sb + SK_AHI + off);
                    ldsm_x4(al, sb + SK_ALO + off);
                    #pragma unroll
                    for (int j = 0; j < 4; j++) {
                        mma_bf16(acc[mi][j], ah, bh[j]);
                        mma_bf16(acc[mi][j], al, bh[j]);
                        mma_bf16(acc[mi][j], ah, bl[j]);
                    }
                }
            }
        }

        // ---- epilogue: bias + sigmoid, direct fragment streaming stores ----
        #pragma unroll
        for (int mi = 0; mi < 4; mi++) {
            const int r0 = bm + wm + mi * 16 + (lane >> 2);
            #pragma unroll
            for (int j = 0; j < 4; j++) {
                const int c0 = bn + wn + j * 8 + 2 * (lane & 3);
                float b0 = (c0     < N) ? __ldg(&bias[c0])     : 0.f;
                float b1 = (c0 + 1 < N) ? __ldg(&bias[c0 + 1]) : 0.f;
                #pragma unroll
                for (int h = 0; h < 2; h++) {
                    int m = r0 + 8 * h;
                    if (m >= M || c0 >= N) continue;
                    float x0 = acc[mi][j][2 * h + 0] + b0;
                    float x1 = acc[mi][j][2 * h + 1] + b1;
                    x0 = 1.f / (1.f + __expf(-x0));
                    x1 = 1.f / (1.f + __expf(-x1));
                    if (c0 + 1 < N) {
                        stcs2(&C[(size_t)m * ldC + c0], make_float2(x0, x1));
                    } else {
                        stcs1(&C[(size_t)m * ldC + c0], x0);
                    }
                }
            }
        }
    }
}

// ---------------- launch ----------------
extern "C" void kernel_launch(void* const* d_in, const int* in_sizes, int n_in,
                              void* d_out, int out_size)
{
    const int*   ei  = (const int*)d_in[0];
    const float* ue  = (const float*)d_in[1];
    const float* it  = (const float*)d_in[2];
    const float* cw1 = (const float*)d_in[3];  const float* cb1 = (const float*)d_in[4];
    const float* cw2 = (const float*)d_in[5];  const float* cb2 = (const float*)d_in[6];
    const float* aw1 = (const float*)d_in[7];  const float* ab1 = (const float*)d_in[8];
    const float* aw2 = (const float*)d_in[9];  const float* ab2 = (const float*)d_in[10];
    const float* sw1 = (const float*)d_in[11]; const float* sb1 = (const float*)d_in[12];
    const float* sw2 = (const float*)d_in[13]; const float* sb2 = (const float*)d_in[14];

    float* out     = (float*)d_out;
    float* o_churn = out;
    float* o_cat   = o_churn + (size_t)NUM_USERS;
    float* o_sku   = o_cat   + (size_t)NUM_USERS * NUM_CAT;
    float* o_u     = o_sku   + (size_t)NUM_USERS * NUM_SKU;

    float *e1, *e2, *b1ptr;
    __nv_bfloat16 *uhi, *ulo, *hhi, *hlo;
    cudaGetSymbolAddress((void**)&e1, g_e1);
    cudaGetSymbolAddress((void**)&e2, g_e2);
    cudaGetSymbolAddress((void**)&uhi, g_Uhi);
    cudaGetSymbolAddress((void**)&ulo, g_Ulo);
    cudaGetSymbolAddress((void**)&hhi, g_Hhi);
    cudaGetSymbolAddress((void**)&hlo, g_Hlo);
    cudaGetSymbolAddress((void**)&b1ptr, g_bias1);

    cudaFuncSetAttribute(k_tmma<0, 1>, cudaFuncAttributeMaxDynamicSharedMemorySize, SMEM_MMA);
    cudaFuncSetAttribute(k_tmma_sku, cudaFuncAttributeMaxDynamicSharedMemorySize, SMEM_SKU);

    const int nb = (N_NODES + T_SCAN - 1) / T_SCAN;

    // graph build
    k_zero<<<(N_NODES + 255) / 256, 256>>>();
    k_deg<<<(N_EDGES + 255) / 256, 256>>>(ei);
    k_scan_part<<<nb, T_SCAN>>>();
    k_scan_base2<<<1, 256>>>(nb);
    k_scan_add<<<nb, T_SCAN>>>();
    k_fill<<<(N_EDGES + 255) / 256, 256>>>(ei);

    // propagation: (ue,it) -> e1 -> e2 -> fused final (u + bf16 split)
    k_prop4_init<<<(N_NODES + 7) / 8, 256>>>((const float4*)ue, (const float4*)it,
                                             (float4*)e1, N_NODES);
    k_prop4<<<(N_NODES + 7) / 8, 256>>>((const float4*)e1, (float4*)e2, N_NODES);
    k_prop_final<<<(NUM_USERS + 7) / 8, 256>>>((const float4*)ue, (const float4*)e1,
                                               (const float4*)e2, (float4*)o_u);

    const int MT = (NUM_USERS + 127) / 128;   // 782
    dim3 blk(256);

    // combined layer-1: B = [cw1 | aw1 | sw1] transposed (rows 0..383), catW2 at rows 384..483.
    // blockIdx.x==0 fuses churn head, ==1 fuses cat head, ==2 writes H planes for sku.
    k_bias1<<<1, HPITCH>>>(cb1, ab1, sb1);
    k_prepB<<<(HID * 128 + 255) / 256, 256>>>(cw1, HID, 0);
    k_prepB<<<(HID * 128 + 255) / 256, 256>>>(aw1, HID, 128);
    k_prepB<<<(HID * 128 + 255) / 256, 256>>>(sw1, HID, 256);
    k_prepB<<<(NUM_CAT * 128 + 255) / 256, 256>>>(aw2, NUM_CAT, 384);
    k_tmma<0, 1><<<dim3(3, MT), blk, SMEM_MMA>>>(uhi, ulo, 128, b1ptr,
                                                 nullptr, 0, hhi, hlo, HPITCH,
                                                 NUM_USERS, HPITCH,
                                                 cw2, cb2, o_churn,
                                                 ab2, o_cat);

    // sku layer-2 (H slice [256,384)), N=2000: A-resident, 8 n-tiles per CTA
    k_prepB<<<(NUM_SKU * 128 + 255) / 256, 256>>>(sw2, NUM_SKU, 484);
    k_tmma_sku<<<dim3((NUM_SKU + SK_NT * 128 - 1) / (SK_NT * 128), MT), blk, SMEM_SKU>>>(
        g_Bthi + 0, g_Btlo + 0, 0, sb2, o_sku, NUM_SKU, NUM_USERS, NUM_SKU);

    // NOTE: the call above is replaced below with the exact r12 wiring (H planes at
    // pitch HPITCH, sku weights at g_Bt rows 0..1999 as in r12). Re-prep sku weights
    // at row 0 to match r12 exactly:
    k_prepB<<<(NUM_SKU * 128 + 255) / 256, 256>>>(sw2, NUM_SKU, 0);
    k_tmma_sku<<<dim3((NUM_SKU + SK_NT * 128 - 1) / (SK_NT * 128), MT), blk, SMEM_SKU>>>(
        hhi + 256, hlo + 256, HPITCH, sb2, o_sku, NUM_SKU, NUM_USERS, NUM_SKU);
}

// round 17
// speedup vs baseline: 13.9283x; 13.9283x over previous
#include <cuda_runtime.h>
#include <cuda_bf16.h>
#include <math.h>
#include <stdint.h>

#define NUM_USERS 100000
#define NUM_ITEMS 50000
#define N_NODES   150000
#define EMBED     128
#define N_EDGES   1000000
#define N_SYM     (2*N_EDGES)
#define HID       128
#define NUM_CAT   100
#define NUM_SKU   2000
#define HPITCH    384

// ---------------- static device scratch ----------------
__device__ int   g_deg[N_NODES];
__device__ int   g_off[N_NODES + 1];
__device__ int   g_cur[N_NODES];
__device__ int   g_adj_col[N_SYM];
__device__ float g_adj_w[N_SYM];
__device__ __align__(16) float g_e1[(size_t)N_NODES * EMBED];
__device__ __align__(16) float g_e2[(size_t)N_NODES * EMBED];
__device__ int   g_bsum[256];
__device__ float g_bias1[HPITCH];
// bf16 split operand buffers
__device__ __align__(16) __nv_bfloat16 g_Uhi[(size_t)NUM_USERS * EMBED];
__device__ __align__(16) __nv_bfloat16 g_Ulo[(size_t)NUM_USERS * EMBED];
__device__ __align__(16) __nv_bfloat16 g_Hhi[(size_t)NUM_USERS * HPITCH];
__device__ __align__(16) __nv_bfloat16 g_Hlo[(size_t)NUM_USERS * HPITCH];
__device__ __align__(16) __nv_bfloat16 g_Bthi[2560 * 128];   // transposed weights [n][k]
__device__ __align__(16) __nv_bfloat16 g_Btlo[2560 * 128];

#define T_SCAN 1024

// ================= warp-MMA / cp.async helpers =================
__device__ __forceinline__ uint32_t smem_u32(const void* p) {
    uint32_t a;
    asm("{ .reg .u64 t; cvta.to.shared.u64 t, %1; cvt.u32.u64 %0, t; }" : "=r"(a) : "l"(p));
    return a;
}
__device__ __forceinline__ void ldsm_x4(uint32_t r[4], uint32_t addr) {
    asm volatile("ldmatrix.sync.aligned.m8n8.x4.shared.b16 {%0,%1,%2,%3}, [%4];"
                 : "=r"(r[0]), "=r"(r[1]), "=r"(r[2]), "=r"(r[3]) : "r"(addr));
}
__device__ __forceinline__ void ldsm_x2(uint32_t r[2], uint32_t addr) {
    asm volatile("ldmatrix.sync.aligned.m8n8.x2.shared.b16 {%0,%1}, [%2];"
                 : "=r"(r[0]), "=r"(r[1]) : "r"(addr));
}
__device__ __forceinline__ void mma_bf16(float c[4], const uint32_t a[4], const uint32_t b[2]) {
    asm volatile("mma.sync.aligned.m16n8k16.row.col.f32.bf16.bf16.f32 "
                 "{%0,%1,%2,%3}, {%4,%5,%6,%7}, {%8,%9}, {%0,%1,%2,%3};"
                 : "+f"(c[0]), "+f"(c[1]), "+f"(c[2]), "+f"(c[3])
                 : "r"(a[0]), "r"(a[1]), "r"(a[2]), "r"(a[3]), "r"(b[0]), "r"(b[1]));
}
// 16B async copy with zero-fill fallback for invalid rows
__device__ __forceinline__ void cp16z(uint32_t dst, const void* src, bool v) {
    if (v) {
        asm volatile("cp.async.cg.shared.global [%0], [%1], 16;" :: "r"(dst), "l"(src) : "memory");
    } else {
        asm volatile("st.shared.v4.b32 [%0], {%1,%1,%1,%1};" :: "r"(dst), "r"(0u) : "memory");
    }
}
#define CP_COMMIT() asm volatile("cp.async.commit_group;" ::: "memory")
#define CP_WAIT0()  asm volatile("cp.async.wait_group 0;" ::: "memory")

// fma helper (function, not macro — avoids token collision with .w member)
__device__ __forceinline__ void fma4(float4& acc, float wt, const float4& v) {
    acc.x = fmaf(wt, v.x, acc.x);
    acc.y = fmaf(wt, v.y, acc.y);
    acc.z = fmaf(wt, v.z, acc.z);
    acc.w = fmaf(wt, v.w, acc.w);
}
// streaming stores (cache .cs — evict-first; output streams never re-read)
__device__ __forceinline__ void stcs4(float4* p, float4 v) {
    asm volatile("st.global.cs.v4.f32 [%0], {%1,%2,%3,%4};"
                 :: "l"(p), "f"(v.x), "f"(v.y), "f"(v.z), "f"(v.w) : "memory");
}
__device__ __forceinline__ void stcs2(float* p, float2 v) {
    asm volatile("st.global.cs.v2.f32 [%0], {%1,%2};"
                 :: "l"(p), "f"(v.x), "f"(v.y) : "memory");
}
__device__ __forceinline__ void stcs1(float* p, float v) {
    asm volatile("st.global.cs.f32 [%0], %1;" :: "l"(p), "f"(v) : "memory");
}

// ---------------- graph build ----------------
__global__ void k_zero() {
    int i = blockIdx.x * blockDim.x + threadIdx.x;
    if (i < N_NODES) { g_deg[i] = 0; g_cur[i] = 0; }
}
__global__ void k_deg(const int* __restrict__ ei) {
    int e = blockIdx.x * blockDim.x + threadIdx.x;
    if (e < N_EDGES) {
        atomicAdd(&g_deg[ei[e]], 1);
        atomicAdd(&g_deg[ei[N_EDGES + e]], 1);
    }
}
__global__ void k_scan_part() {
    __shared__ int s[T_SCAN];
    int t = threadIdx.x, b = blockIdx.x;
    int i = b * T_SCAN + t;
    int v = (i < N_NODES) ? g_deg[i] : 0;
    s[t] = v;
    __syncthreads();
    for (int d = 1; d < T_SCAN; d <<= 1) {
        int x = (t >= d) ? s[t - d] : 0;
        __syncthreads();
        s[t] += x;
        __syncthreads();
    }
    if (i < N_NODES) g_off[i] = s[t] - v;
    if (t == T_SCAN - 1) g_bsum[b] = s[t];
}
__global__ void k_scan_base2(int nb) {
    __shared__ int s[256];
    int t = threadIdx.x;
    int v = (t < nb) ? g_bsum[t] : 0;
    s[t] = v;
    __syncthreads();
    for (int d = 1; d < 256; d <<= 1) {
        int x = (t >= d) ? s[t - d] : 0;
        __syncthreads();
        s[t] += x;
        __syncthreads();
    }
    if (t < nb) g_bsum[t] = s[t] - v;   // exclusive
    if (t == 255) g_off[N_NODES] = s[255];
}
__global__ void k_scan_add() {
    int i = blockIdx.x * T_SCAN + threadIdx.x;
    if (i < N_NODES) g_off[i] += g_bsum[blockIdx.x];
}
__global__ void k_fill(const int* __restrict__ ei) {
    int e = blockIdx.x * blockDim.x + threadIdx.x;
    if (e >= N_EDGES) return;
    int r = ei[e];
    int c = ei[N_EDGES + e];
    float nrm = rsqrtf((float)g_deg[r]) * rsqrtf((float)g_deg[c]);
    int p = atomicAdd(&g_cur[r], 1);
    g_adj_col[g_off[r] + p] = c; g_adj_w[g_off[r] + p] = nrm;
    int q = atomicAdd(&g_cur[c], 1);
    g_adj_col[g_off[c] + q] = r; g_adj_w[g_off[c] + q] = nrm;
}

// ---------------- propagation: one warp per row, float4 lanes ----------------
__device__ __forceinline__ float4 prop_row(const float4* __restrict__ src, int row, int lane) {
    int s = g_off[row], e2 = g_off[row + 1];
    float4 a = make_float4(0.f, 0.f, 0.f, 0.f);
    int e = s;
    for (; e + 4 <= e2; e += 4) {
        int   c0 = g_adj_col[e],   c1 = g_adj_col[e+1], c2 = g_adj_col[e+2], c3 = g_adj_col[e+3];
        float w0 = g_adj_w[e],     w1 = g_adj_w[e+1],   w2 = g_adj_w[e+2],   w3 = g_adj_w[e+3];
        float4 v0 = src[c0 * 32 + lane];
        float4 v1 = src[c1 * 32 + lane];
        float4 v2 = src[c2 * 32 + lane];
        float4 v3 = src[c3 * 32 + lane];
        fma4(a, w0, v0); fma4(a, w1, v1); fma4(a, w2, v2); fma4(a, w3, v3);
    }
    for (; e < e2; e++) {
        float4 v = src[g_adj_col[e] * 32 + lane];
        fma4(a, g_adj_w[e], v);
    }
    return a;
}

// layer-1: gather directly from ue/it (no e0 buffer)
__device__ __forceinline__ const float4* node_ptr(const float4* __restrict__ ue,
                                                  const float4* __restrict__ it, int c) {
    return (c < NUM_USERS) ? (ue + (size_t)c * 32) : (it + ((size_t)c - NUM_USERS) * 32);
}

__global__ void k_prop4_init(const float4* __restrict__ ue, const float4* __restrict__ it,
                             float4* __restrict__ dst, int nrows) {
    int warp = (blockIdx.x * blockDim.x + threadIdx.x) >> 5;
    int lane = threadIdx.x & 31;
    if (warp >= nrows) return;
    int s = g_off[warp], e2 = g_off[warp + 1];
    float4 a = make_float4(0.f, 0.f, 0.f, 0.f);
    int e = s;
    for (; e + 4 <= e2; e += 4) {
        int   c0 = g_adj_col[e],   c1 = g_adj_col[e+1], c2 = g_adj_col[e+2], c3 = g_adj_col[e+3];
        float w0 = g_adj_w[e],     w1 = g_adj_w[e+1],   w2 = g_adj_w[e+2],   w3 = g_adj_w[e+3];
        float4 v0 = node_ptr(ue, it, c0)[lane];
        float4 v1 = node_ptr(ue, it, c1)[lane];
        float4 v2 = node_ptr(ue, it, c2)[lane];
        float4 v3 = node_ptr(ue, it, c3)[lane];
        fma4(a, w0, v0); fma4(a, w1, v1); fma4(a, w2, v2); fma4(a, w3, v3);
    }
    for (; e < e2; e++) {
        float4 v = node_ptr(ue, it, g_adj_col[e])[lane];
        fma4(a, g_adj_w[e], v);
    }
    stcs4(&dst[warp * 32 + lane], a);
}

__global__ void k_prop4(const float4* __restrict__ src, float4* __restrict__ dst, int nrows) {
    int warp = (blockIdx.x * blockDim.x + threadIdx.x) >> 5;
    int lane = threadIdx.x & 31;
    if (warp >= nrows) return;
    float4 a = prop_row(src, warp, lane);
    stcs4(&dst[warp * 32 + lane], a);
}

// final layer (users only): a = prop(e2); u = (ue+e1+e2+a)/4; write u fp32 + bf16 hi/lo
__global__ void k_prop_final(const float4* __restrict__ ue, const float4* __restrict__ e1,
                             const float4* __restrict__ e2, float4* __restrict__ uo) {
    int warp = (blockIdx.x * blockDim.x + threadIdx.x) >> 5;
    int lane = threadIdx.x & 31;
    if (warp >= NUM_USERS) return;
    float4 a = prop_row(e2, warp, lane);
    float4 v0 = ue[warp * 32 + lane];
    float4 v1 = e1[warp * 32 + lane];
    float4 v2 = e2[warp * 32 + lane];
    float4 u;
    u.x = (v0.x + v1.x + v2.x + a.x) * 0.25f;
    u.y = (v0.y + v1.y + v2.y + a.y) * 0.25f;
    u.z = (v0.z + v1.z + v2.z + a.z) * 0.25f;
    u.w = (v0.w + v1.w + v2.w + a.w) * 0.25f;
    stcs4(&uo[warp * 32 + lane], u);
    __nv_bfloat16 h0 = __float2bfloat16(u.x), h1 = __float2bfloat16(u.y);
    __nv_bfloat16 h2 = __float2bfloat16(u.z), h3 = __float2bfloat16(u.w);
    __nv_bfloat16 l0 = __float2bfloat16(u.x - __bfloat162float(h0));
    __nv_bfloat16 l1 = __float2bfloat16(u.y - __bfloat162float(h1));
    __nv_bfloat16 l2 = __float2bfloat16(u.z - __bfloat162float(h2));
    __nv_bfloat16 l3 = __float2bfloat16(u.w - __bfloat162float(h3));
    __nv_bfloat162 hp0 = {h0, h1}, hp1 = {h2, h3};
    __nv_bfloat162 lp0 = {l0, l1}, lp1 = {l2, l3};
    uint2 hv, lv;
    hv.x = *(uint32_t*)&hp0; hv.y = *(uint32_t*)&hp1;
    lv.x = *(uint32_t*)&lp0; lv.y = *(uint32_t*)&lp1;
    *(uint2*)&g_Uhi[(size_t)warp * 128 + lane * 4] = hv;
    *(uint2*)&g_Ulo[(size_t)warp * 128 + lane * 4] = lv;
}

// weights: B [K=128, N] row-major -> transposed bf16 hi/lo rows [dstOff+n][k]
__global__ void k_prepB(const float* __restrict__ B, int N, int dstOff) {
    int i = blockIdx.x * blockDim.x + threadIdx.x;
    if (i >= N * 128) return;
    int n = i >> 7, k = i & 127;
    float v = B[(size_t)k * N + n];
    __nv_bfloat16 h = __float2bfloat16(v);
    g_Bthi[(dstOff + n) * 128 + k] = h;
    g_Btlo[(dstOff + n) * 128 + k] = __float2bfloat16(v - __bfloat162float(h));
}
__global__ void k_bias1(const float* __restrict__ b0, const float* __restrict__ b1,
                        const float* __restrict__ b2) {
    int i = threadIdx.x;
    g_bias1[i] = (i < 128) ? b0[i] : ((i < 256) ? b1[i - 128] : b2[i - 256]);
}

// ---------------- warp-MMA bf16-split GEMM, 128x128 tile (layer-1, heads fused) ----------------
// MODE 1, grid (3, MT): blockIdx.x==0 -> fused churn head; ==1 -> fused cat head (second
// in-smem GEMM vs catW2 at g_Bt rows [384,484)); ==2 -> bf16 hi/lo H planes for sku.
#define SA_HI 0
#define SA_LO 16384
#define SB_HI 32768
#define SB_LO 49152
// fused-cat phase overlays:
#define FC_HH  0        // 32 KB: H hi plane, 2 kt blocks of 16 KB
#define FC_HL  32768    // 32 KB: H lo plane
#define FC_B2H 65536    // 16 KB: catW2 hi, one kt-half
#define FC_B2L 81920    // 16 KB
#define OPITCH 132
#define SMEM_MMA 98304

template <int ACT, int MODE>
__global__ void __launch_bounds__(256, 2) k_tmma(
    const __nv_bfloat16* __restrict__ Ahi, const __nv_bfloat16* __restrict__ Alo, int lda,
    const float* __restrict__ bias, float* __restrict__ C, int ldC,
    __nv_bfloat16* __restrict__ Phi, __nv_bfloat16* __restrict__ Plo, int ldP,
    int M, int N,
    const float* __restrict__ churn_w2, const float* __restrict__ churn_b2,
    float* __restrict__ churn_out,
    const float* __restrict__ cat_bias, float* __restrict__ cat_out)
{
    extern __shared__ char sm[];
    const uint32_t sb = smem_u32(sm);
    const int tid  = threadIdx.x;
    const int wid  = tid >> 5;
    const int lane = tid & 31;
    const int bm = blockIdx.y * 128;
    const int bn = blockIdx.x * 128;
    const int wm = (wid >> 2) * 64;
    const int wn = (wid & 3) * 32;

    float acc[4][4][4];
    #pragma unroll
    for (int i = 0; i < 4; i++)
        #pragma unroll
        for (int j = 0; j < 4; j++)
            #pragma unroll
            for (int t = 0; t < 4; t++) acc[i][j][t] = 0.f;

    for (int kt = 0; kt < 128; kt += 64) {
        #pragma unroll
        for (int it = 0; it < 4; it++) {
            int idx = tid + it * 256;
            int r = idx >> 3, c = idx & 7;
            uint32_t dst = (uint32_t)(r * 128 + ((c ^ (r & 7)) << 4));
            int gr = bm + r;
            bool av = gr < M;
            cp16z(sb + SA_HI + dst, Ahi + (size_t)gr * lda + kt + c * 8, av);
            cp16z(sb + SA_LO + dst, Alo + (size_t)gr * lda + kt + c * 8, av);
            int gn = bn + r;
            bool bv = gn < N;
            cp16z(sb + SB_HI + dst, g_Bthi + (size_t)gn * 128 + kt + c * 8, bv);
            cp16z(sb + SB_LO + dst, g_Btlo + (size_t)gn * 128 + kt + c * 8, bv);
        }
        CP_COMMIT();
        CP_WAIT0();
        __syncthreads();

        #pragma unroll
        for (int ks = 0; ks < 4; ks++) {
            const int k0 = ks * 16;
            uint32_t bh[4][2], bl[4][2];
            const int k_l = k0 + ((lane & 8) ? 8 : 0);
            #pragma unroll
            for (int j = 0; j < 4; j++) {
                int row = wn + j * 8 + (lane & 7);
                uint32_t off = (uint32_t)(row * 128 + (((k_l >> 3) ^ (row & 7)) << 4));
                ldsm_x2(bh[j], sb + SB_HI + off);
                ldsm_x2(bl[j], sb + SB_LO + off);
            }
            #pragma unroll
            for (int mi = 0; mi < 4; mi++) {
                const int m_l = wm + mi * 16 + (lane & 7) + (lane & 8);
                const int k_a = k0 + ((lane & 16) ? 8 : 0);
                const uint32_t off = (uint32_t)(m_l * 128 + (((k_a >> 3) ^ (m_l & 7)) << 4));
                uint32_t ah[4], al[4];
                ldsm_x4(ah, sb + SA_HI + off);
                ldsm_x4(al, sb + SA_LO + off);
                #pragma unroll
                for (int j = 0; j < 4; j++) {
                    mma_bf16(acc[mi][j], ah, bh[j]);
                    mma_bf16(acc[mi][j], al, bh[j]);
                    mma_bf16(acc[mi][j], ah, bl[j]);
                }
            }
        }
        __syncthreads();
    }

    // ---- fused churn head (blockIdx.x == 0 of layer-1) ----
    if (MODE == 1 && churn_out != nullptr && blockIdx.x == 0) {
        float* churnS = (float*)sm;
        if (tid < 128) churnS[tid] = 0.f;
        __syncthreads();
        #pragma unroll
        for (int mi = 0; mi < 4; mi++) {
            float p0 = 0.f, p1 = 0.f;   // rows r0 and r0+8
            #pragma unroll
            for (int j = 0; j < 4; j++) {
                int c0 = wn + j * 8 + 2 * (lane & 3);
                float wv0 = __ldg(&churn_w2[c0]);
                float wv1 = __ldg(&churn_w2[c0 + 1]);
                float b0 = __ldg(&bias[c0]);
                float b1 = __ldg(&bias[c0 + 1]);
                float x00 = fmaxf(acc[mi][j][0] + b0, 0.f);
                float x01 = fmaxf(acc[mi][j][1] + b1, 0.f);
                float x10 = fmaxf(acc[mi][j][2] + b0, 0.f);
                float x11 = fmaxf(acc[mi][j][3] + b1, 0.f);
                p0 = fmaf(x00, wv0, p0); p0 = fmaf(x01, wv1, p0);
                p1 = fmaf(x10, wv0, p1); p1 = fmaf(x11, wv1, p1);
            }
            p0 += __shfl_xor_sync(0xFFFFFFFF, p0, 1);
            p0 += __shfl_xor_sync(0xFFFFFFFF, p0, 2);
            p1 += __shfl_xor_sync(0xFFFFFFFF, p1, 1);
            p1 += __shfl_xor_sync(0xFFFFFFFF, p1, 2);
            if ((lane & 3) == 0) {
                int r0 = wm + mi * 16 + (lane >> 2);
                atomicAdd(&churnS[r0], p0);
                atomicAdd(&churnS[r0 + 8], p1);
            }
        }
        __syncthreads();
        if (tid < 128) {
            int m = bm + tid;
            if (m < M)
                churn_out[m] = 1.f / (1.f + __expf(-(churnS[tid] + churn_b2[0])));
        }
        return;
    }

    // ---- fused cat head (blockIdx.x == 1 of layer-1) ----
    if (MODE == 1 && cat_out != nullptr && blockIdx.x == 1) {
        // stage relu(H + bias) as swizzled bf16 hi/lo planes (full K=128, 2 kt blocks)
        #pragma unroll
        for (int mi = 0; mi < 4; mi++) {
            const int r0 = wm + mi * 16 + (lane >> 2);
            #pragma unroll
            for (int j = 0; j < 4; j++) {
                const int c0 = wn + j * 8 + 2 * (lane & 3);
                float b0 = __ldg(&bias[128 + c0]);
                float b1 = __ldg(&bias[128 + c0 + 1]);
                const int ktb = c0 >> 6, cc = c0 & 63;
                #pragma unroll
                for (int h = 0; h < 2; h++) {
                    int r = r0 + 8 * h;
                    float x0 = fmaxf(acc[mi][j][2 * h + 0] + b0, 0.f);
                    float x1 = fmaxf(acc[mi][j][2 * h + 1] + b1, 0.f);
                    __nv_bfloat16 h0 = __float2bfloat16(x0), h1 = __float2bfloat16(x1);
                    __nv_bfloat16 l0 = __float2bfloat16(x0 - __bfloat162float(h0));
                    __nv_bfloat16 l1 = __float2bfloat16(x1 - __bfloat162float(h1));
                    __nv_bfloat162 hp = {h0, h1}, lp = {l0, l1};
                    uint32_t off = (uint32_t)(ktb * 16384 + r * 128 +
                                              (((cc >> 3) ^ (r & 7)) << 4) + (cc & 7) * 2);
                    *(uint32_t*)(sm + FC_HH + off) = *(uint32_t*)&hp;
                    *(uint32_t*)(sm + FC_HL + off) = *(uint32_t*)&lp;
                }
            }
        }
        // second GEMM: cat = H @ catW2^T   (catW2 bf16-split at g_Bt rows [384,484))
        float acc2[4][4][4];
        #pragma unroll
        for (int i = 0; i < 4; i++)
            #pragma unroll
            for (int j = 0; j < 4; j++)
                #pragma unroll
                for (int t = 0; t < 4; t++) acc2[i][j][t] = 0.f;

        #pragma unroll
        for (int ktb = 0; ktb < 2; ktb++) {
            __syncthreads();   // H staged (ktb=0) / protect B2 buffer from prev readers
            #pragma unroll
            for (int it = 0; it < 4; it++) {
                int idx = tid + it * 256;
                int r = idx >> 3, c = idx & 7;
                uint32_t dst = (uint32_t)(r * 128 + ((c ^ (r & 7)) << 4));
                bool bv = r < NUM_CAT;
                cp16z(sb + FC_B2H + dst, g_Bthi + (size_t)(384 + r) * 128 + ktb * 64 + c * 8, bv);
                cp16z(sb + FC_B2L + dst, g_Btlo + (size_t)(384 + r) * 128 + ktb * 64 + c * 8, bv);
            }
            CP_COMMIT();
            CP_WAIT0();
            __syncthreads();

            #pragma unroll
            for (int ks = 0; ks < 4; ks++) {
                const int k0 = ks * 16;
                uint32_t bh[4][2], bl[4][2];
                const int k_l = k0 + ((lane & 8) ? 8 : 0);
                #pragma unroll
                for (int j = 0; j < 4; j++) {
                    int row = wn + j * 8 + (lane & 7);
                    uint32_t off = (uint32_t)(row * 128 + (((k_l >> 3) ^ (row & 7)) << 4));
                    ldsm_x2(bh[j], sb + FC_B2H + off);
                    ldsm_x2(bl[j], sb + FC_B2L + off);
                }
                #pragma unroll
                for (int mi = 0; mi < 4; mi++) {
                    const int m_l = wm + mi * 16 + (lane & 7) + (lane & 8);
                    const int k_a = k0 + ((lane & 16) ? 8 : 0);
                    const uint32_t off = (uint32_t)(ktb * 16384 + m_l * 128 +
                                                    (((k_a >> 3) ^ (m_l & 7)) << 4));
                    uint32_t ah[4], al[4];
                    ldsm_x4(ah, sb + FC_HH + off);
                    ldsm_x4(al, sb + FC_HL + off);
                    #pragma unroll
                    for (int j = 0; j < 4; j++) {
                        mma_bf16(acc2[mi][j], ah, bh[j]);
                        mma_bf16(acc2[mi][j], al, bh[j]);
                        mma_bf16(acc2[mi][j], ah, bl[j]);
                    }
                }
            }
        }
        __syncthreads();   // all smem MMA reads done before outS overwrites H region

        // epilogue: sigmoid -> staged smem -> coalesced fp32 stores (N = NUM_CAT)
        float* outS = (float*)sm;
        #pragma unroll
        for (int mi = 0; mi < 4; mi++) {
            const int r0 = wm + mi * 16 + (lane >> 2);
            #pragma unroll
            for (int j = 0; j < 4; j++) {
                const int c0 = wn + j * 8 + 2 * (lane & 3);
                float b0 = (c0     < NUM_CAT) ? __ldg(&cat_bias[c0])     : 0.f;
                float b1 = (c0 + 1 < NUM_CAT) ? __ldg(&cat_bias[c0 + 1]) : 0.f;
                #pragma unroll
                for (int h = 0; h < 2; h++) {
                    float x0 = acc2[mi][j][2 * h + 0] + b0;
                    float x1 = acc2[mi][j][2 * h + 1] + b1;
                    x0 = 1.f / (1.f + __expf(-x0));
                    x1 = 1.f / (1.f + __expf(-x1));
                    outS[(r0 + 8 * h) * OPITCH + c0]     = x0;
                    outS[(r0 + 8 * h) * OPITCH + c0 + 1] = x1;
                }
            }
        }
        __syncthreads();
        for (int idx = tid; idx < 128 * 32; idx += 256) {
            int r = idx >> 5;
            int col = (idx & 31) * 4;
            int m = bm + r;
            if (m >= M || col >= NUM_CAT) continue;
            float4 v = *(float4*)&outS[r * OPITCH + col];
            stcs4((float4*)&cat_out[(size_t)m * NUM_CAT + col], v);
        }
        return;
    }

    // ---- standard epilogue: bias + act -> smem staging -> coalesced stores ----
    float* outS = (float*)sm;
    #pragma unroll
    for (int mi = 0; mi < 4; mi++) {
        const int r0 = wm + mi * 16 + (lane >> 2);
        #pragma unroll
        for (int j = 0; j < 4; j++) {
            const int c0 = wn + j * 8 + 2 * (lane & 3);
            float b0 = (bn + c0     < N) ? __ldg(&bias[bn + c0])     : 0.f;
            float b1 = (bn + c0 + 1 < N) ? __ldg(&bias[bn + c0 + 1]) : 0.f;
            #pragma unroll
            for (int h = 0; h < 2; h++) {
                float x0 = acc[mi][j][2 * h + 0] + b0;
                float x1 = acc[mi][j][2 * h + 1] + b1;
                if (ACT == 0) { x0 = fmaxf(x0, 0.f); x1 = fmaxf(x1, 0.f); }
                else { x0 = 1.f / (1.f + __expf(-x0)); x1 = 1.f / (1.f + __expf(-x1)); }
                outS[(r0 + 8 * h) * OPITCH + c0]     = x0;
                outS[(r0 + 8 * h) * OPITCH + c0 + 1] = x1;
            }
        }
    }
    __syncthreads();

    const int Nvalid = min(128, N - bn);
    for (int idx = tid; idx < 128 * 32; idx += 256) {
        int r = idx >> 5;
        int col = (idx & 31) * 4;
        int m = bm + r;
        if (m >= M || col >= Nvalid) continue;
        float4 v = *(float4*)&outS[r * OPITCH + col];
        if (MODE == 0) {
            *(float4*)&C[(size_t)m * ldC + bn + col] = v;
        } else {
            __nv_bfloat16 h0 = __float2bfloat16(v.x), h1 = __float2bfloat16(v.y);
            __nv_bfloat16 h2 = __float2bfloat16(v.z), h3 = __float2bfloat16(v.w);
            __nv_bfloat16 l0 = __float2bfloat16(v.x - __bfloat162float(h0));
            __nv_bfloat16 l1 = __float2bfloat16(v.y - __bfloat162float(h1));
            __nv_bfloat16 l2 = __float2bfloat16(v.z - __bfloat162float(h2));
            __nv_bfloat16 l3 = __float2bfloat16(v.w - __bfloat162float(h3));
            __nv_bfloat162 hp0 = {h0, h1}, hp1 = {h2, h3};
            __nv_bfloat162 lp0 = {l0, l1}, lp1 = {l2, l3};
            uint2 hv, lv;
            hv.x = *(uint32_t*)&hp0; hv.y = *(uint32_t*)&hp1;
            lv.x = *(uint32_t*)&lp0; lv.y = *(uint32_t*)&lp1;
            *(uint2*)&Phi[(size_t)m * ldP + bn + col] = hv;
            *(uint2*)&Plo[(size_t)m * ldP + bn + col] = lv;
        }
    }
}

// ---------------- sku layer-2: A-resident N-loop GEMM, 128x128 tiles, SK_NT tiles/CTA ----------------
#define SK_AHI 0          // 2 kt blocks of 16KB -> 32KB
#define SK_ALO 32768      // 32KB
#define SK_BHI 65536      // 16KB
#define SK_BLO 81920      // 16KB
#define SMEM_SKU 98304
#define SK_NT 8

__global__ void __launch_bounds__(256, 2) k_tmma_sku(
    const __nv_bfloat16* __restrict__ Ahi, const __nv_bfloat16* __restrict__ Alo, int lda,
    const float* __restrict__ bias, float* __restrict__ C, int ldC,
    int M, int N)
{
    extern __shared__ char sm[];
    const uint32_t sb = smem_u32(sm);
    const int tid  = threadIdx.x;
    const int wid  = tid >> 5;
    const int lane = tid & 31;
    const int bm = blockIdx.y * 128;
    const int bn0 = blockIdx.x * (SK_NT * 128);
    const int wm = (wid >> 2) * 64;
    const int wn = (wid & 3) * 32;

    // ---- load A tile once: full K=128, hi+lo planes (kt blocks stacked) ----
    #pragma unroll
    for (int it = 0; it < 8; it++) {
        int idx = tid + it * 256;          // 0..2047 per plane
        int r = idx >> 4, cc = idx & 15;
        int ktb = cc >> 3, c = cc & 7;
        uint32_t dst = (uint32_t)(ktb * 16384 + r * 128 + ((c ^ (r & 7)) << 4));
        int gr = bm + r;
        bool av = gr < M;
        cp16z(sb + SK_AHI + dst, Ahi + (size_t)gr * lda + ktb * 64 + c * 8, av);
        cp16z(sb + SK_ALO + dst, Alo + (size_t)gr * lda + ktb * 64 + c * 8, av);
    }
    CP_COMMIT();

    for (int nt = 0; nt < SK_NT; nt++) {
        const int bn = bn0 + nt * 128;

        float acc[4][4][4];
        #pragma unroll
        for (int i = 0; i < 4; i++)
            #pragma unroll
            for (int j = 0; j < 4; j++)
                #pragma unroll
                for (int t = 0; t < 4; t++) acc[i][j][t] = 0.f;

        #pragma unroll
        for (int ktb = 0; ktb < 2; ktb++) {
            __syncthreads();   // protect B buffer from previous iteration's readers
            #pragma unroll
            for (int it = 0; it < 4; it++) {
                int idx = tid + it * 256;     // 0..1023 per plane
                int r = idx >> 3, c = idx & 7;
                uint32_t dst = (uint32_t)(r * 128 + ((c ^ (r & 7)) << 4));
                int gn = bn + r;
                bool bv = gn < N;
                cp16z(sb + SK_BHI + dst, g_Bthi + (size_t)gn * 128 + ktb * 64 + c * 8, bv);
                cp16z(sb + SK_BLO + dst, g_Btlo + (size_t)gn * 128 + ktb * 64 + c * 8, bv);
            }
            CP_COMMIT();
            CP_WAIT0();        // waits B (and A on first pass)
            __syncthreads();

            #pragma unroll
            for (int ks = 0; ks < 4; ks++) {
                const int k0 = ks * 16;
                uint32_t bh[4][2], bl[4][2];
                const int k_l = k0 + ((lane & 8) ? 8 : 0);
                #pragma unroll
                for (int j = 0; j < 4; j++) {
                    int row = wn + j * 8 + (lane & 7);
                    uint32_t off = (uint32_t)(row * 128 + (((k_l >> 3) ^ (row & 7)) << 4));
                    ldsm_x2(bh[j], sb + SK_BHI + off);
                    ldsm_x2(bl[j], sb + SK_BLO + off);
                }
                #pragma unroll
                for (int mi = 0; mi < 4; mi++) {
                    const int m_l = wm + mi * 16 + (lane & 7) + (lane & 8);
                    const int k_a = k0 + ((lane & 16) ? 8 : 0);
                    const uint32_t off = (uint32_t)(ktb * 16384 + m_l * 128 + (((k_a >> 3) ^ (m_l & 7)) << 4));
                    uint32_t ah[4], al[4];
                    ldsm_x4(ah, sb + SK_AHI + off);
                    ldsm_x4(al, sb + SK_ALO + off);
                    #pragma unroll
                    for (int j = 0; j < 4; j++) {
                        mma_bf16(acc[mi][j], ah, bh[j]);
                        mma_bf16(acc[mi][j], al, bh[j]);
                        mma_bf16(acc[mi][j], ah, bl[j]);
                    }
                }
            }
        }

        // ---- epilogue: bias + sigmoid, direct fragment streaming stores ----
        #pragma unroll
        for (int mi = 0; mi < 4; mi++) {
            const int r0 = bm + wm + mi * 16 + (lane >> 2);
            #pragma unroll
            for (int j = 0; j < 4; j++) {
                const int c0 = bn + wn + j * 8 + 2 * (lane & 3);
                float b0 = (c0     < N) ? __ldg(&bias[c0])     : 0.f;
                float b1 = (c0 + 1 < N) ? __ldg(&bias[c0 + 1]) : 0.f;
                #pragma unroll
                for (int h = 0; h < 2; h++) {
                    int m = r0 + 8 * h;
                    if (m >= M || c0 >= N) continue;
                    float x0 = acc[mi][j][2 * h + 0] + b0;
                    float x1 = acc[mi][j][2 * h + 1] + b1;
                    x0 = 1.f / (1.f + __expf(-x0));
                    x1 = 1.f / (1.f + __expf(-x1));
                    if (c0 + 1 < N) {
                        stcs2(&C[(size_t)m * ldC + c0], make_float2(x0, x1));
                    } else {
                        stcs1(&C[(size_t)m * ldC + c0], x0);
                    }
                }
            }
        }
    }
}

// ---------------- launch ----------------
extern "C" void kernel_launch(void* const* d_in, const int* in_sizes, int n_in,
                              void* d_out, int out_size)
{
    const int*   ei  = (const int*)d_in[0];
    const float* ue  = (const float*)d_in[1];
    const float* it  = (const float*)d_in[2];
    const float* cw1 = (const float*)d_in[3];  const float* cb1 = (const float*)d_in[4];
    const float* cw2 = (const float*)d_in[5];  const float* cb2 = (const float*)d_in[6];
    const float* aw1 = (const float*)d_in[7];  const float* ab1 = (const float*)d_in[8];
    const float* aw2 = (const float*)d_in[9];  const float* ab2 = (const float*)d_in[10];
    const float* sw1 = (const float*)d_in[11]; const float* sb1 = (const float*)d_in[12];
    const float* sw2 = (const float*)d_in[13]; const float* sb2 = (const float*)d_in[14];

    float* out     = (float*)d_out;
    float* o_churn = out;
    float* o_cat   = o_churn + (size_t)NUM_USERS;
    float* o_sku   = o_cat   + (size_t)NUM_USERS * NUM_CAT;
    float* o_u     = o_sku   + (size_t)NUM_USERS * NUM_SKU;

    float *e1, *e2, *b1ptr;
    __nv_bfloat16 *uhi, *ulo, *hhi, *hlo;
    cudaGetSymbolAddress((void**)&e1, g_e1);
    cudaGetSymbolAddress((void**)&e2, g_e2);
    cudaGetSymbolAddress((void**)&uhi, g_Uhi);
    cudaGetSymbolAddress((void**)&ulo, g_Ulo);
    cudaGetSymbolAddress((void**)&hhi, g_Hhi);
    cudaGetSymbolAddress((void**)&hlo, g_Hlo);
    cudaGetSymbolAddress((void**)&b1ptr, g_bias1);

    cudaFuncSetAttribute(k_tmma<0, 1>, cudaFuncAttributeMaxDynamicSharedMemorySize, SMEM_MMA);
    cudaFuncSetAttribute(k_tmma_sku, cudaFuncAttributeMaxDynamicSharedMemorySize, SMEM_SKU);

    const int nb = (N_NODES + T_SCAN - 1) / T_SCAN;

    // graph build
    k_zero<<<(N_NODES + 255) / 256, 256>>>();
    k_deg<<<(N_EDGES + 255) / 256, 256>>>(ei);
    k_scan_part<<<nb, T_SCAN>>>();
    k_scan_base2<<<1, 256>>>(nb);
    k_scan_add<<<nb, T_SCAN>>>();
    k_fill<<<(N_EDGES + 255) / 256, 256>>>(ei);

    // propagation: (ue,it) -> e1 -> e2 -> fused final (u + bf16 split)
    k_prop4_init<<<(N_NODES + 7) / 8, 256>>>((const float4*)ue, (const float4*)it,
                                             (float4*)e1, N_NODES);
    k_prop4<<<(N_NODES + 7) / 8, 256>>>((const float4*)e1, (float4*)e2, N_NODES);
    k_prop_final<<<(NUM_USERS + 7) / 8, 256>>>((const float4*)ue, (const float4*)e1,
                                               (const float4*)e2, (float4*)o_u);

    const int MT = (NUM_USERS + 127) / 128;   // 782
    dim3 blk(256);

    // combined layer-1: B = [cw1 | aw1 | sw1] transposed (rows 0..383), catW2 at rows 384..483.
    // blockIdx.x==0 fuses churn head, ==1 fuses cat head, ==2 writes H planes for sku.
    k_bias1<<<1, HPITCH>>>(cb1, ab1, sb1);
    k_prepB<<<(HID * 128 + 255) / 256, 256>>>(cw1, HID, 0);
    k_prepB<<<(HID * 128 + 255) / 256, 256>>>(aw1, HID, 128);
    k_prepB<<<(HID * 128 + 255) / 256, 256>>>(sw1, HID, 256);
    k_prepB<<<(NUM_CAT * 128 + 255) / 256, 256>>>(aw2, NUM_CAT, 384);
    k_tmma<0, 1><<<dim3(3, MT), blk, SMEM_MMA>>>(uhi, ulo, 128, b1ptr,
                                                 nullptr, 0, hhi, hlo, HPITCH,
                                                 NUM_USERS, HPITCH,
                                                 cw2, cb2, o_churn,
                                                 ab2, o_cat);

    // sku layer-2 (H slice [256,384)), N=2000: A-resident, 8 n-tiles per CTA
    k_prepB<<<(NUM_SKU * 128 + 255) / 256, 256>>>(sw2, NUM_SKU, 0);
    k_tmma_sku<<<dim3((NUM_SKU + SK_NT * 128 - 1) / (SK_NT * 128), MT), blk, SMEM_SKU>>>(
        hhi + 256, hlo + 256, HPITCH, sb2, o_sku, NUM_SKU, NUM_USERS, NUM_SKU);
}